// round 2
// baseline (speedup 1.0000x reference)
#include <cuda_runtime.h>
#include <math.h>

#define DD 512
#define MM 2048
#define BB 4
#define KK 8
#define NN 8192
#define MB_ (MM*BB)               // 8192 floats per h_all row
#define RPB 8                     // rows per block
#define NEG_INF (-1e30f)
#define EPSV 1e-8f

// Scratch (device globals: allocation-free rule)
__device__ float g_Vt[(size_t)MM*BB*DD];   // 16 MB: Vt[(m*B+b)*D + d]
__device__ float g_esum[MM];
__device__ float g_counts[MM];
__device__ float g_acc[3];                 // cap, rec, unc (sums over rows)
__device__ unsigned g_done;

// Tiled transpose V (D, M*B) -> Vt (M*B, D); block (0,0) also zeroes accumulators.
__global__ void transpose_kernel(const float* __restrict__ V) {
    __shared__ float tile[32][33];
    if (blockIdx.x == 0 && blockIdx.y == 0) {
        int t = threadIdx.y * 32 + threadIdx.x;
        #pragma unroll
        for (int j = 0; j < 8; j++) { g_esum[t + 256*j] = 0.0f; g_counts[t + 256*j] = 0.0f; }
        if (t < 3) g_acc[t] = 0.0f;
        if (t == 0) g_done = 0u;
    }
    int mb0 = blockIdx.x * 32;
    int d0  = blockIdx.y * 32;
    int tx = threadIdx.x, ty = threadIdx.y;   // 32 x 8
    #pragma unroll
    for (int i = 0; i < 32; i += 8)
        tile[ty + i][tx] = V[(size_t)(d0 + ty + i) * MB_ + mb0 + tx];
    __syncthreads();
    #pragma unroll
    for (int i = 0; i < 32; i += 8)
        g_Vt[(size_t)(mb0 + ty + i) * DD + d0 + tx] = tile[tx][ty + i];
}

// Fused main: energy -> top-K (register/shuffle) -> outputs -> x_hat scalars -> last-block finalize.
__global__ __launch_bounds__(256)
void main_kernel(const float* __restrict__ x_flat,
                 const float* __restrict__ h_all,
                 float* __restrict__ out) {
    __shared__ float cand_v[64];
    __shared__ int   cand_m[64];
    __shared__ int   sel_idx[KK];
    __shared__ float hs_sh[KK * BB];
    __shared__ float red_a[8];
    __shared__ float red_b[8];
    __shared__ unsigned s_last;

    const int t = threadIdx.x;
    const int warp = t >> 5, lane = t & 31;
    const int mbase = warp * 256 + lane;        // thread's m set: mbase + 32*j

    float esum[8];
    #pragma unroll
    for (int j = 0; j < 8; j++) esum[j] = 0.0f;
    float blk_cap = 0.0f, blk_rec = 0.0f, blk_unc = 0.0f;

    float* out_hs  = out;                          // (N, K, B)
    float* out_idx = out + (size_t)NN * KK * BB;   // (N, K) as float

    for (int r = 0; r < RPB; r++) {
        const int n = blockIdx.x * RPB + r;
        const float4* hrow = (const float4*)(h_all + (size_t)n * MB_);

        // ---- Phase A: energies in registers (streaming loads) ----
        float e[8];
        #pragma unroll
        for (int j = 0; j < 8; j++) {
            float4 h = __ldcs(&hrow[mbase + 32 * j]);
            e[j] = h.x*h.x + h.y*h.y + h.z*h.z + h.w*h.w;
            esum[j] += e[j];
        }

        // ---- Phase B1: warp-local top-8 (no barriers, no LDS) ----
        #pragma unroll
        for (int kk = 0; kk < KK; kk++) {
            float bv = e[0]; int bj = 0;
            #pragma unroll
            for (int j = 1; j < 8; j++) if (e[j] > bv) { bv = e[j]; bj = j; }
            int bm = mbase + 32 * bj;
            #pragma unroll
            for (int off = 16; off; off >>= 1) {
                float ov = __shfl_down_sync(0xffffffffu, bv, off);
                int   om = __shfl_down_sync(0xffffffffu, bm, off);
                if (ov > bv || (ov == bv && om < bm)) { bv = ov; bm = om; }
            }
            int   win  = __shfl_sync(0xffffffffu, bm, 0);
            float winv = __shfl_sync(0xffffffffu, bv, 0);
            if ((win & 31) == lane) e[(win >> 5) & 7] = NEG_INF;
            if (lane == 0) { cand_v[warp * 8 + kk] = winv; cand_m[warp * 8 + kk] = win; }
        }
        __syncthreads();   // #1: candidates visible

        // ---- Phase B2: warp 0 merges 64 candidates -> global top-8 + Phase C ----
        if (warp == 0) {
            float c0 = cand_v[lane], c1 = cand_v[lane + 32];
            int   m0 = cand_m[lane], m1 = cand_m[lane + 32];
            float capsum = 0.0f;
            #pragma unroll
            for (int kk = 0; kk < KK; kk++) {
                float bv; int bm;
                if (c0 > c1 || (c0 == c1 && m0 < m1)) { bv = c0; bm = m0; }
                else                                   { bv = c1; bm = m1; }
                #pragma unroll
                for (int off = 16; off; off >>= 1) {
                    float ov = __shfl_down_sync(0xffffffffu, bv, off);
                    int   om = __shfl_down_sync(0xffffffffu, bm, off);
                    if (ov > bv || (ov == bv && om < bm)) { bv = ov; bm = om; }
                }
                int win = __shfl_sync(0xffffffffu, bm, 0);
                if (lane == 0) { sel_idx[kk] = win; capsum += bv; }
                if (m0 == win) c0 = NEG_INF;
                if (m1 == win) c1 = NEG_INF;
            }
            if (lane == 0) blk_cap += capsum;
            __syncwarp();
            if (lane < KK) {
                int m = sel_idx[lane];
                out_idx[(size_t)n * KK + lane] = (float)m;
                float4 h = hrow[m];   // L2 hit (just streamed)
                ((float4*)hs_sh)[lane] = h;
                ((float4*)(out_hs + (size_t)n * KK * BB))[lane] = h;
                atomicAdd(&g_counts[m], 1.0f);
            }
        }
        __syncthreads();   // #2: sel_idx + hs_sh ready

        // ---- Phase D: x_hat + residual scalars (each thread owns 2 d's) ----
        const int d0 = 2 * t;
        float ax = 0.0f, ay = 0.0f;
        #pragma unroll
        for (int kk = 0; kk < KK; kk++) {
            const int m = sel_idx[kk];
            const float* vb = g_Vt + (size_t)m * BB * DD + d0;
            #pragma unroll
            for (int b = 0; b < BB; b++) {
                float hv = hs_sh[kk * BB + b];
                float2 v = *(const float2*)(vb + b * DD);
                ax += hv * v.x;
                ay += hv * v.y;
            }
        }
        float2 xv = __ldcs((const float2*)(x_flat + (size_t)n * DD + d0));
        float rx = xv.x - ax, ry = xv.y - ay;
        float punc = rx * rx + ry * ry;
        float prec = ax * ax + ay * ay;
        #pragma unroll
        for (int off = 16; off; off >>= 1) {
            punc += __shfl_down_sync(0xffffffffu, punc, off);
            prec += __shfl_down_sync(0xffffffffu, prec, off);
        }
        if (lane == 0) { red_a[warp] = punc; red_b[warp] = prec; }
        __syncthreads();   // #3: reductions ready
        if (t == 0) {
            float su = 0.0f, sr = 0.0f;
            #pragma unroll
            for (int w = 0; w < 8; w++) { su += red_a[w]; sr += red_b[w]; }
            blk_unc += su; blk_rec += sr;
        }
    }

    // ---- flush block accumulators ----
    #pragma unroll
    for (int j = 0; j < 8; j++)
        atomicAdd(&g_esum[mbase + 32 * j], esum[j]);
    if (t == 0) {
        atomicAdd(&g_acc[0], blk_cap);
        atomicAdd(&g_acc[1], blk_rec);
        atomicAdd(&g_acc[2], blk_unc);
    }
    __threadfence();
    __syncthreads();
    if (t == 0) s_last = (atomicAdd(&g_done, 1u) == gridDim.x - 1) ? 1u : 0u;
    __syncthreads();
    if (!s_last) return;

    // ---- last-block finalize (replaces final_kernel) ----
    {
        float s = 0.0f;
        #pragma unroll
        for (int j = 0; j < 8; j++) s += __ldcg(&g_esum[t + 256 * j]);
        #pragma unroll
        for (int off = 16; off; off >>= 1) s += __shfl_down_sync(0xffffffffu, s, off);
        if (lane == 0) red_a[warp] = s;
        __syncthreads();
        __shared__ float s_denom;
        if (t == 0) {
            float tot = 0.0f;
            #pragma unroll
            for (int w = 0; w < 8; w++) tot += red_a[w];
            s_denom = fmaxf(tot / (float)NN, EPSV);
        }
        __syncthreads();
        const float denom = s_denom;

        float ent = 0.0f, low = 0.0f, dead = 0.0f;
        const float expected = (float)KK / (float)MM * (float)NN;  // 32
        #pragma unroll
        for (int j = 0; j < 8; j++) {
            int m = t + 256 * j;
            float avg = __ldcg(&g_esum[m]) / (float)NN;
            float p = fmaxf(avg / denom, EPSV);
            ent += -p * logf(p);
            float c = __ldcg(&g_counts[m]);
            if (c <= 0.1f * expected)  low  += 1.0f;
            if (c <= 0.01f * expected) dead += 1.0f;
        }
        #pragma unroll
        for (int off = 16; off; off >>= 1) {
            ent  += __shfl_down_sync(0xffffffffu, ent,  off);
            low  += __shfl_down_sync(0xffffffffu, low,  off);
            dead += __shfl_down_sync(0xffffffffu, dead, off);
        }
        if (lane == 0) { red_a[warp] = ent; red_b[warp] = low; cand_v[warp] = dead; }
        __syncthreads();
        if (t == 0) {
            float E = 0.0f, L = 0.0f, Dd = 0.0f;
            #pragma unroll
            for (int w = 0; w < 8; w++) { E += red_a[w]; L += red_b[w]; Dd += cand_v[w]; }
            float entropy = E / logf((float)MM);
            float cap = __ldcg(&g_acc[0]) / (float)NN;
            float rec = __ldcg(&g_acc[1]) / (float)NN;
            float unc = __ldcg(&g_acc[2]) / (float)NN;
            size_t OFF = (size_t)NN * KK * BB + (size_t)NN * KK;  // 327680
            out[OFF + 0] = cap;
            out[OFF + 1] = rec;
            out[OFF + 2] = unc;
            out[OFF + 3] = entropy;
            out[OFF + 4] = unc + 0.01f * (1.0f - entropy);
            out[OFF + 5] = L;
            out[OFF + 6] = Dd;
        }
    }
}

extern "C" void kernel_launch(void* const* d_in, const int* in_sizes, int n_in,
                              void* d_out, int out_size) {
    const float* x_flat = (const float*)d_in[0];   // (N, D)
    const float* h_all  = (const float*)d_in[1];   // (N, M, B)
    const float* V      = (const float*)d_in[2];   // (D, M, B)
    float* out = (float*)d_out;

    dim3 tb(32, 8);
    dim3 tg(MB_ / 32, DD / 32);    // (256, 16)
    transpose_kernel<<<tg, tb>>>(V);

    main_kernel<<<NN / RPB, 256>>>(x_flat, h_all, out);
}

// round 3
// speedup vs baseline: 1.3377x; 1.3377x over previous
#include <cuda_runtime.h>
#include <math.h>

#define DD 512
#define MM 2048
#define BB 4
#define KK 8
#define NN 8192
#define MB_ (MM*BB)               // 8192 floats per h_all row
#define RPB 4                     // rows per block
#define EPSV 1e-8f

// Scratch (device globals: allocation-free rule)
__device__ float g_Vt[(size_t)MM*BB*DD];   // 16 MB: Vt[(m*B+b)*D + d]
__device__ float g_esum[MM];
__device__ float g_counts[MM];
__device__ float g_acc[3];                 // cap, rec, unc (sums over rows)
__device__ unsigned g_done;

// Tiled transpose V (D, M*B) -> Vt (M*B, D); block (0,0) also zeroes accumulators.
__global__ void transpose_kernel(const float* __restrict__ V) {
    __shared__ float tile[32][33];
    if (blockIdx.x == 0 && blockIdx.y == 0) {
        int t = threadIdx.y * 32 + threadIdx.x;
        #pragma unroll
        for (int j = 0; j < 8; j++) { g_esum[t + 256*j] = 0.0f; g_counts[t + 256*j] = 0.0f; }
        if (t < 3) g_acc[t] = 0.0f;
        if (t == 0) g_done = 0u;
    }
    int mb0 = blockIdx.x * 32;
    int d0  = blockIdx.y * 32;
    int tx = threadIdx.x, ty = threadIdx.y;   // 32 x 8
    #pragma unroll
    for (int i = 0; i < 32; i += 8)
        tile[ty + i][tx] = V[(size_t)(d0 + ty + i) * MB_ + mb0 + tx];
    __syncthreads();
    #pragma unroll
    for (int i = 0; i < 32; i += 8)
        g_Vt[(size_t)(mb0 + ty + i) * DD + d0 + tx] = tile[tx][ty + i];
}

// warp argmax over (value-bits desc, index asc): 2 REDUX ops, no shuffle chain.
__device__ __forceinline__ void warp_argmax(unsigned vbits, int m,
                                            unsigned &win_v, int &win_m) {
    unsigned mx = __reduce_max_sync(0xffffffffu, vbits);
    unsigned cand = (vbits == mx) ? (unsigned)m : 0xffffffffu;
    win_m = (int)__reduce_min_sync(0xffffffffu, cand);
    win_v = mx;
}

__global__ __launch_bounds__(256)
void main_kernel(const float* __restrict__ x_flat,
                 const float* __restrict__ h_all,
                 float* __restrict__ out) {
    __shared__ unsigned cv[2][64];   // candidate value bits (double-buffered by row parity)
    __shared__ int      cm[2][64];   // candidate expert indices
    __shared__ float    red_a[8], red_b[8];
    __shared__ unsigned s_last;

    const int t = threadIdx.x;
    const int warp = t >> 5, lane = t & 31;
    const int mbase = warp * 256 + lane;      // thread's m set: mbase + 32*j, j=0..7

    float esum[8];
    #pragma unroll
    for (int j = 0; j < 8; j++) esum[j] = 0.0f;
    float unc_acc = 0.0f, rec_acc = 0.0f, cap_acc = 0.0f;

    float* out_hs  = out;                          // (N, K, B)
    float* out_idx = out + (size_t)NN * KK * BB;   // (N, K) as float

    for (int r = 0; r < RPB; r++) {
        const int n = blockIdx.x * RPB + r;
        const int buf = r & 1;
        const float4* hrow = (const float4*)(h_all + (size_t)n * MB_);

        // ---- Phase A: energies (streaming loads, bits kept for ordinal top-k) ----
        unsigned eb[8];
        #pragma unroll
        for (int j = 0; j < 8; j++) {
            float4 h = __ldcs(&hrow[mbase + 32 * j]);
            float e = fmaf(h.x, h.x, fmaf(h.y, h.y, fmaf(h.z, h.z, h.w * h.w)));
            esum[j] += e;
            eb[j] = __float_as_uint(e);           // e >= 0 -> bits monotone
        }

        // ---- Phase B1: warp-local top-8 (REDUX argmax, no barriers) ----
        #pragma unroll
        for (int kk = 0; kk < KK; kk++) {
            unsigned bv = eb[0]; int bj = 0;
            #pragma unroll
            for (int j = 1; j < 8; j++) if (eb[j] > bv) { bv = eb[j]; bj = j; }
            int bm = mbase + 32 * bj;
            unsigned wv; int wm;
            warp_argmax(bv, bm, wv, wm);
            if ((wm & 31) == lane) eb[(wm >> 5) & 7] = 0u;
            if (lane == 0) { cv[buf][warp * 8 + kk] = wv; cm[buf][warp * 8 + kk] = wm; }
        }
        __syncthreads();   // the ONLY barrier per row: candidates visible

        // ---- Phase B2: ALL warps redundantly merge 64 candidates -> sel[8] (uniform regs) ----
        unsigned c0 = cv[buf][lane],      c1 = cv[buf][lane + 32];
        int      m0 = cm[buf][lane],      m1 = cm[buf][lane + 32];
        int sel[KK];
        #pragma unroll
        for (int kk = 0; kk < KK; kk++) {
            bool p0 = (c0 > c1) || (c0 == c1 && m0 < m1);
            unsigned bv = p0 ? c0 : c1;
            int      bm = p0 ? m0 : m1;
            unsigned wv; int wm;
            warp_argmax(bv, bm, wv, wm);
            sel[kk] = wm;
            if (warp == 0 && lane == 0) cap_acc += __uint_as_float(wv);
            if (m0 == wm) c0 = 0u;
            if (m1 == wm) c1 = 0u;
        }

        // ---- Phase C: warp 0 writes per-row outputs (coalesced, lane kk owns kk) ----
        if (warp == 0 && lane < KK) {
            int mym = sel[0];
            #pragma unroll
            for (int kk = 1; kk < KK; kk++) if (lane == kk) mym = sel[kk];
            out_idx[(size_t)n * KK + lane] = (float)mym;
            float4 h = hrow[mym];
            ((float4*)(out_hs + (size_t)n * KK * BB))[lane] = h;
            atomicAdd(&g_counts[mym], 1.0f);
        }

        // ---- Phase D: x_hat + residual; per-lane accumulation only (no reduce, no barrier) ----
        const int d0 = 2 * t;
        float ax = 0.0f, ay = 0.0f;
        #pragma unroll
        for (int kk = 0; kk < KK; kk++) {
            const int m = sel[kk];
            float4 h = hrow[m];                    // uniform address, L1/L2 hit
            const float* vb = g_Vt + (size_t)m * (BB * DD) + d0;
            float2 v0 = *(const float2*)(vb);
            float2 v1 = *(const float2*)(vb + DD);
            float2 v2 = *(const float2*)(vb + 2 * DD);
            float2 v3 = *(const float2*)(vb + 3 * DD);
            ax += h.x * v0.x + h.y * v1.x + h.z * v2.x + h.w * v3.x;
            ay += h.x * v0.y + h.y * v1.y + h.z * v2.y + h.w * v3.y;
        }
        float2 xv = __ldcs((const float2*)(x_flat + (size_t)n * DD + d0));
        float rx = xv.x - ax, ry = xv.y - ay;
        unc_acc += rx * rx + ry * ry;
        rec_acc += ax * ax + ay * ay;
    }

    // ---- flush block accumulators (once per kernel) ----
    #pragma unroll
    for (int j = 0; j < 8; j++)
        atomicAdd(&g_esum[mbase + 32 * j], esum[j]);
    // warp-reduce unc/rec once
    #pragma unroll
    for (int off = 16; off; off >>= 1) {
        unc_acc += __shfl_down_sync(0xffffffffu, unc_acc, off);
        rec_acc += __shfl_down_sync(0xffffffffu, rec_acc, off);
    }
    if (lane == 0) {
        atomicAdd(&g_acc[2], unc_acc);
        atomicAdd(&g_acc[1], rec_acc);
        if (warp == 0) atomicAdd(&g_acc[0], cap_acc);
    }
    __threadfence();
    __syncthreads();
    if (t == 0) s_last = (atomicAdd(&g_done, 1u) == gridDim.x - 1) ? 1u : 0u;
    __syncthreads();
    if (!s_last) return;

    // ---- last-block finalize ----
    {
        float s = 0.0f;
        #pragma unroll
        for (int j = 0; j < 8; j++) s += __ldcg(&g_esum[t + 256 * j]);
        #pragma unroll
        for (int off = 16; off; off >>= 1) s += __shfl_down_sync(0xffffffffu, s, off);
        if (lane == 0) red_a[warp] = s;
        __syncthreads();
        __shared__ float s_denom;
        if (t == 0) {
            float tot = 0.0f;
            #pragma unroll
            for (int w = 0; w < 8; w++) tot += red_a[w];
            s_denom = fmaxf(tot / (float)NN, EPSV);
        }
        __syncthreads();
        const float denom = s_denom;

        float ent = 0.0f, low = 0.0f, dead = 0.0f;
        const float expected = (float)KK / (float)MM * (float)NN;  // 32
        #pragma unroll
        for (int j = 0; j < 8; j++) {
            int m = t + 256 * j;
            float avg = __ldcg(&g_esum[m]) / (float)NN;
            float p = fmaxf(avg / denom, EPSV);
            ent += -p * logf(p);
            float c = __ldcg(&g_counts[m]);
            if (c <= 0.1f * expected)  low  += 1.0f;
            if (c <= 0.01f * expected) dead += 1.0f;
        }
        #pragma unroll
        for (int off = 16; off; off >>= 1) {
            ent  += __shfl_down_sync(0xffffffffu, ent,  off);
            low  += __shfl_down_sync(0xffffffffu, low,  off);
            dead += __shfl_down_sync(0xffffffffu, dead, off);
        }
        if (lane == 0) { red_a[warp] = ent; red_b[warp] = low; cv[0][warp] = __float_as_uint(dead); }
        __syncthreads();
        if (t == 0) {
            float E = 0.0f, L = 0.0f, Dd = 0.0f;
            #pragma unroll
            for (int w = 0; w < 8; w++) {
                E += red_a[w]; L += red_b[w]; Dd += __uint_as_float(cv[0][w]);
            }
            float entropy = E / logf((float)MM);
            float cap = __ldcg(&g_acc[0]) / (float)NN;
            float rec = __ldcg(&g_acc[1]) / (float)NN;
            float unc = __ldcg(&g_acc[2]) / (float)NN;
            size_t OFF = (size_t)NN * KK * BB + (size_t)NN * KK;  // 327680
            out[OFF + 0] = cap;
            out[OFF + 1] = rec;
            out[OFF + 2] = unc;
            out[OFF + 3] = entropy;
            out[OFF + 4] = unc + 0.01f * (1.0f - entropy);
            out[OFF + 5] = L;
            out[OFF + 6] = Dd;
        }
    }
}

extern "C" void kernel_launch(void* const* d_in, const int* in_sizes, int n_in,
                              void* d_out, int out_size) {
    const float* x_flat = (const float*)d_in[0];   // (N, D)
    const float* h_all  = (const float*)d_in[1];   // (N, M, B)
    const float* V      = (const float*)d_in[2];   // (D, M, B)
    float* out = (float*)d_out;

    dim3 tb(32, 8);
    dim3 tg(MB_ / 32, DD / 32);    // (256, 16)
    transpose_kernel<<<tg, tb>>>(V);

    main_kernel<<<NN / RPB, 256>>>(x_flat, h_all, out);
}

// round 4
// speedup vs baseline: 1.6111x; 1.2044x over previous
#include <cuda_runtime.h>
#include <math.h>

#define DD 512
#define MM 2048
#define BB 4
#define KK 8
#define NN 8192
#define MB_ (MM*BB)               // 8192 floats per h_all row
#define RPB 4                     // rows per block (2 pairs)
#define EPSV 1e-8f

// Scratch (device globals: allocation-free rule)
__device__ float g_Vt[(size_t)MM*BB*DD];   // 16 MB: Vt[(m*B+b)*D + d]
__device__ float g_esum[MM];
__device__ float g_counts[MM];
__device__ float g_acc[3];                 // cap, rec, unc (sums over rows)
__device__ unsigned g_done;

// Tiled transpose V (D, M*B) -> Vt (M*B, D); block (0,0) also zeroes accumulators.
__global__ void transpose_kernel(const float* __restrict__ V) {
    __shared__ float tile[32][33];
    if (blockIdx.x == 0 && blockIdx.y == 0) {
        int t = threadIdx.y * 32 + threadIdx.x;
        #pragma unroll
        for (int j = 0; j < 8; j++) { g_esum[t + 256*j] = 0.0f; g_counts[t + 256*j] = 0.0f; }
        if (t < 3) g_acc[t] = 0.0f;
        if (t == 0) g_done = 0u;
    }
    int mb0 = blockIdx.x * 32;
    int d0  = blockIdx.y * 32;
    int tx = threadIdx.x, ty = threadIdx.y;   // 32 x 8
    #pragma unroll
    for (int i = 0; i < 32; i += 8)
        tile[ty + i][tx] = V[(size_t)(d0 + ty + i) * MB_ + mb0 + tx];
    __syncthreads();
    #pragma unroll
    for (int i = 0; i < 32; i += 8)
        g_Vt[(size_t)(mb0 + ty + i) * DD + d0 + tx] = tile[tx][ty + i];
}

// warp argmax over (value-bits desc, index asc): REDUX pair.
__device__ __forceinline__ void warp_argmax(unsigned vbits, int m,
                                            unsigned &win_v, int &win_m) {
    unsigned mx = __reduce_max_sync(0xffffffffu, vbits);
    unsigned cand = (vbits == mx) ? (unsigned)m : 0xffffffffu;
    win_m = (int)__reduce_min_sync(0xffffffffu, cand);
    win_v = mx;
}

__global__ __launch_bounds__(256)
void main_kernel(const float* __restrict__ x_flat,
                 const float* __restrict__ h_all,
                 float* __restrict__ out) {
    __shared__ unsigned cvA[2][64], cvB[2][64];
    __shared__ int      cmA[2][64], cmB[2][64];
    __shared__ float    red_a[8], red_b[8];
    __shared__ unsigned s_last;

    const int t = threadIdx.x;
    const int warp = t >> 5, lane = t & 31;
    const int mbase = warp * 256 + lane;      // thread's m set: mbase + 32*j

    float esum[8];
    #pragma unroll
    for (int j = 0; j < 8; j++) esum[j] = 0.0f;
    float unc_acc = 0.0f, rec_acc = 0.0f, cap_acc = 0.0f;

    float* out_hs  = out;                          // (N, K, B)
    float* out_idx = out + (size_t)NN * KK * BB;   // (N, K) as float

    const int half = warp >> 2;                    // 0: row A, 1: row B duty
    const int t2 = t & 127;                        // thread index within half
    const int d0 = 4 * t2;                         // 4 d's per thread in Phase D

    #pragma unroll
    for (int pair = 0; pair < RPB / 2; pair++) {
        const int nA = blockIdx.x * RPB + 2 * pair;
        const int nB = nA + 1;
        const float4* hrowA = (const float4*)(h_all + (size_t)nA * MB_);
        const float4* hrowB = (const float4*)(h_all + (size_t)nB * MB_);

        // ---- Phase A: energies for both rows (high MLP streaming loads) ----
        unsigned ebA[8], ebB[8];
        #pragma unroll
        for (int j = 0; j < 8; j++) {
            float4 a = __ldcs(&hrowA[mbase + 32 * j]);
            float4 b = __ldcs(&hrowB[mbase + 32 * j]);
            float ea = fmaf(a.x, a.x, fmaf(a.y, a.y, fmaf(a.z, a.z, a.w * a.w)));
            float ec = fmaf(b.x, b.x, fmaf(b.y, b.y, fmaf(b.z, b.z, b.w * b.w)));
            esum[j] += ea + ec;
            ebA[j] = __float_as_uint(ea);
            ebB[j] = __float_as_uint(ec);
        }

        // ---- Phase B1: warp-local top-8, two interleaved independent chains ----
        #pragma unroll
        for (int kk = 0; kk < KK; kk++) {
            // row A
            unsigned bvA = ebA[0]; int bjA = 0;
            #pragma unroll
            for (int j = 1; j < 8; j++) if (ebA[j] > bvA) { bvA = ebA[j]; bjA = j; }
            int bmA = mbase + 32 * bjA;
            // row B
            unsigned bvB = ebB[0]; int bjB = 0;
            #pragma unroll
            for (int j = 1; j < 8; j++) if (ebB[j] > bvB) { bvB = ebB[j]; bjB = j; }
            int bmB = mbase + 32 * bjB;

            unsigned wvA; int wmA;
            warp_argmax(bvA, bmA, wvA, wmA);
            unsigned wvB; int wmB;
            warp_argmax(bvB, bmB, wvB, wmB);

            #pragma unroll
            for (int j = 0; j < 8; j++) {
                if (wmA == mbase + 32 * j) ebA[j] = 0u;
                if (wmB == mbase + 32 * j) ebB[j] = 0u;
            }
            if (lane == 0) {
                cvA[pair & 1][warp * 8 + kk] = wvA; cmA[pair & 1][warp * 8 + kk] = wmA;
                cvB[pair & 1][warp * 8 + kk] = wvB; cmB[pair & 1][warp * 8 + kk] = wmB;
            }
        }
        __syncthreads();   // the ONLY barrier per pair

        // ---- Phase B2: warps 0-3 merge row A, warps 4-7 merge row B ----
        const unsigned* cv = half ? cvB[pair & 1] : cvA[pair & 1];
        const int*      cm = half ? cmB[pair & 1] : cmA[pair & 1];
        unsigned c0 = cv[lane], c1 = cv[lane + 32];
        int      m0 = cm[lane], m1 = cm[lane + 32];
        int sel[KK];
        #pragma unroll
        for (int kk = 0; kk < KK; kk++) {
            bool p0 = (c0 > c1) || (c0 == c1 && m0 < m1);
            unsigned bv = p0 ? c0 : c1;
            int      bm = p0 ? m0 : m1;
            unsigned wv; int wm;
            warp_argmax(bv, bm, wv, wm);
            sel[kk] = wm;
            if ((warp & 3) == 0 && lane == 0) cap_acc += __uint_as_float(wv);
            if (m0 == wm) c0 = 0u;
            if (m1 == wm) c1 = 0u;
        }

        const int n = half ? nB : nA;
        const float4* hrow = half ? hrowB : hrowA;

        // ---- Phase C: warp 0 writes row A outputs, warp 4 writes row B ----
        if ((warp & 3) == 0 && lane < KK) {
            int mym = sel[0];
            #pragma unroll
            for (int kk = 1; kk < KK; kk++) if (lane == kk) mym = sel[kk];
            out_idx[(size_t)n * KK + lane] = (float)mym;
            float4 h = hrow[mym];
            ((float4*)(out_hs + (size_t)n * KK * BB))[lane] = h;
            atomicAdd(&g_counts[mym], 1.0f);
        }

        // ---- Phase D: 128 threads per row, 4 d's each, float4 gathers ----
        float ax = 0.0f, ay = 0.0f, az = 0.0f, aw = 0.0f;
        #pragma unroll
        for (int kk = 0; kk < KK; kk++) {
            const int m = sel[kk];
            float4 h = hrow[m];                    // uniform address, cache hit
            const float* vb = g_Vt + (size_t)m * (BB * DD) + d0;
            float4 v0 = *(const float4*)(vb);
            float4 v1 = *(const float4*)(vb + DD);
            float4 v2 = *(const float4*)(vb + 2 * DD);
            float4 v3 = *(const float4*)(vb + 3 * DD);
            ax += h.x * v0.x + h.y * v1.x + h.z * v2.x + h.w * v3.x;
            ay += h.x * v0.y + h.y * v1.y + h.z * v2.y + h.w * v3.y;
            az += h.x * v0.z + h.y * v1.z + h.z * v2.z + h.w * v3.z;
            aw += h.x * v0.w + h.y * v1.w + h.z * v2.w + h.w * v3.w;
        }
        float4 xv = __ldcs((const float4*)(x_flat + (size_t)n * DD + d0));
        float rx = xv.x - ax, ry = xv.y - ay, rz = xv.z - az, rw = xv.w - aw;
        unc_acc += rx * rx + ry * ry + rz * rz + rw * rw;
        rec_acc += ax * ax + ay * ay + az * az + aw * aw;
    }

    // ---- flush block accumulators (once per kernel) ----
    #pragma unroll
    for (int j = 0; j < 8; j++)
        atomicAdd(&g_esum[mbase + 32 * j], esum[j]);
    #pragma unroll
    for (int off = 16; off; off >>= 1) {
        unc_acc += __shfl_down_sync(0xffffffffu, unc_acc, off);
        rec_acc += __shfl_down_sync(0xffffffffu, rec_acc, off);
    }
    if (lane == 0) {
        atomicAdd(&g_acc[2], unc_acc);
        atomicAdd(&g_acc[1], rec_acc);
        if ((warp & 3) == 0) atomicAdd(&g_acc[0], cap_acc);
    }
    __threadfence();
    __syncthreads();
    if (t == 0) s_last = (atomicAdd(&g_done, 1u) == gridDim.x - 1) ? 1u : 0u;
    __syncthreads();
    if (!s_last) return;

    // ---- last-block finalize ----
    {
        float s = 0.0f;
        #pragma unroll
        for (int j = 0; j < 8; j++) s += __ldcg(&g_esum[t + 256 * j]);
        #pragma unroll
        for (int off = 16; off; off >>= 1) s += __shfl_down_sync(0xffffffffu, s, off);
        if (lane == 0) red_a[warp] = s;
        __syncthreads();
        __shared__ float s_denom;
        if (t == 0) {
            float tot = 0.0f;
            #pragma unroll
            for (int w = 0; w < 8; w++) tot += red_a[w];
            s_denom = fmaxf(tot / (float)NN, EPSV);
        }
        __syncthreads();
        const float denom = s_denom;

        float ent = 0.0f, low = 0.0f, dead = 0.0f;
        const float expected = (float)KK / (float)MM * (float)NN;  // 32
        #pragma unroll
        for (int j = 0; j < 8; j++) {
            int m = t + 256 * j;
            float avg = __ldcg(&g_esum[m]) / (float)NN;
            float p = fmaxf(avg / denom, EPSV);
            ent += -p * logf(p);
            float c = __ldcg(&g_counts[m]);
            if (c <= 0.1f * expected)  low  += 1.0f;
            if (c <= 0.01f * expected) dead += 1.0f;
        }
        #pragma unroll
        for (int off = 16; off; off >>= 1) {
            ent  += __shfl_down_sync(0xffffffffu, ent,  off);
            low  += __shfl_down_sync(0xffffffffu, low,  off);
            dead += __shfl_down_sync(0xffffffffu, dead, off);
        }
        if (lane == 0) { red_a[warp] = ent; red_b[warp] = low; cvA[0][warp] = __float_as_uint(dead); }
        __syncthreads();
        if (t == 0) {
            float E = 0.0f, L = 0.0f, Dd = 0.0f;
            #pragma unroll
            for (int w = 0; w < 8; w++) {
                E += red_a[w]; L += red_b[w]; Dd += __uint_as_float(cvA[0][w]);
            }
            float entropy = E / logf((float)MM);
            float cap = __ldcg(&g_acc[0]) / (float)NN;
            float rec = __ldcg(&g_acc[1]) / (float)NN;
            float unc = __ldcg(&g_acc[2]) / (float)NN;
            size_t OFF = (size_t)NN * KK * BB + (size_t)NN * KK;  // 327680
            out[OFF + 0] = cap;
            out[OFF + 1] = rec;
            out[OFF + 2] = unc;
            out[OFF + 3] = entropy;
            out[OFF + 4] = unc + 0.01f * (1.0f - entropy);
            out[OFF + 5] = L;
            out[OFF + 6] = Dd;
        }
    }
}

extern "C" void kernel_launch(void* const* d_in, const int* in_sizes, int n_in,
                              void* d_out, int out_size) {
    const float* x_flat = (const float*)d_in[0];   // (N, D)
    const float* h_all  = (const float*)d_in[1];   // (N, M, B)
    const float* V      = (const float*)d_in[2];   // (D, M, B)
    float* out = (float*)d_out;

    dim3 tb(32, 8);
    dim3 tg(MB_ / 32, DD / 32);    // (256, 16)
    transpose_kernel<<<tg, tb>>>(V);

    main_kernel<<<NN / RPB, 256>>>(x_flat, h_all, out);
}